// round 9
// baseline (speedup 1.0000x reference)
#include <cuda_runtime.h>
#include <cuda_bf16.h>

#define B_    32
#define T_    512
#define N_    128
#define BN_   4096
#define K_    4
#define PMAX_ 64
#define MINP_ 16
#define CMAX_ 32   // T/MINP

#define GATHERED_ELEMS 33554432ull   // 32*128*4*32*64
#define KAMP_OFFSET    67108864ull   // 2 * GATHERED_ELEMS

#define SQ 521                       // padded seq row stride

// Twiddle tables W_512^e = exp(-2*pi*i*e/512), precomputed once (L2-resident)
__device__ float g_twr[256],  g_twi[256];    // e = j
__device__ float g_tw2r[128], g_tw2i[128];   // e = 2j
__device__ float g_t4r[32],   g_t4i[32];     // e = 4k
__device__ float g_t4br[32],  g_t4bi[32];    // e = 4k+128
__device__ float g_t8r[32],   g_t8i[32];     // e = 8k
__device__ float g_wstr[32],  g_wsti[32];    // warp stages: [0..15]=16j [16..23]=32j [24..27]=64j

// One table entry per thread, float sincospif (MUFU), 4 parallel blocks.
__global__ void pt_init() {
    int idx = blockIdx.x * 128 + threadIdx.x;
    float s, c;
    if (idx < 256) {
        sincospif(-(float)idx / 256.f, &s, &c);
        g_twr[idx] = c;  g_twi[idx] = s;
    } else if (idx < 384) {
        int j = idx - 256;
        sincospif(-(float)(2 * j) / 256.f, &s, &c);
        g_tw2r[j] = c;  g_tw2i[j] = s;
    } else if (idx < 416) {
        int k = idx - 384;
        sincospif(-(float)(4 * k) / 256.f, &s, &c);
        g_t4r[k] = c;  g_t4i[k] = s;
    } else if (idx < 448) {
        int k = idx - 416;
        sincospif(-(float)(4 * k + 128) / 256.f, &s, &c);
        g_t4br[k] = c;  g_t4bi[k] = s;
    } else if (idx < 480) {
        int k = idx - 448;
        sincospif(-(float)(8 * k) / 256.f, &s, &c);
        g_t8r[k] = c;  g_t8i[k] = s;
    } else if (idx < 496) {
        int t = idx - 480;
        sincospif(-(float)(16 * t) / 256.f, &s, &c);
        g_wstr[t] = c;  g_wsti[t] = s;
    } else if (idx < 504) {
        int t = idx - 496;
        sincospif(-(float)(32 * t) / 256.f, &s, &c);
        g_wstr[16 + t] = c;  g_wsti[16 + t] = s;
    } else if (idx < 508) {
        int t = idx - 504;
        sincospif(-(float)(64 * t) / 256.f, &s, &c);
        g_wstr[24 + t] = c;  g_wsti[24 + t] = s;
    }
}

// ---------------------------------------------------------------------------
// Fused kernel: one block (256 threads) per FOUR sequences (n-quad).
// Input via float4 loads (4x fewer L1 wavefronts/seq). DIF radix-4 FFT, two
// rounds of 2 FFTs through one shared workspace; register 32-pt sub-FFTs.
// Amplitudes land in ampS[seq][256] (idx 0 = freq 256, idx t = freq brev9(2t)).
// Gather: row-per-warp, stride-1 smem reads; mask: float4 streaming stores.
// ---------------------------------------------------------------------------
__global__ __launch_bounds__(256, 8) void pt_fused(const float* __restrict__ x,
                                                   float* __restrict__ out) {
    __shared__ float seq[4][SQ];                // natural-order sequences
    __shared__ float re[1024], im[1024];        // workspace for 2 FFTs
    __shared__ float ampS[4][256];              // per-seq amplitude candidates
    __shared__ int   sP[4][4], sCyc[4][4], sBase[4][4];

    const int bn0  = blockIdx.x * 4;
    const int tid  = threadIdx.x;
    const int lane = tid & 31;
    const int wid  = tid >> 5;

    // ---- load 4 sequences: one float4 across the n-quad per timestep ----
    {
        const int b  = bn0 >> 7;
        const int n0 = bn0 & 127;
        const float4* xp = (const float4*)(x + (size_t)b * T_ * N_ + n0);
        float4 v0 = xp[(size_t)tid * (N_ / 4)];
        float4 v1 = xp[(size_t)(tid + 256) * (N_ / 4)];
        seq[0][tid] = v0.x;  seq[1][tid] = v0.y;
        seq[2][tid] = v0.z;  seq[3][tid] = v0.w;
        seq[0][tid + 256] = v1.x;  seq[1][tid + 256] = v1.y;
        seq[2][tid + 256] = v1.z;  seq[3][tid + 256] = v1.w;
    }
    __syncthreads();

    const int f    = tid >> 7;          // which FFT of the round (0/1)
    const int base = f << 9;
    const int tl   = tid & 127;

    // ---- two rounds of 2 FFTs each ----
#pragma unroll
    for (int r = 0; r < 2; r++) {
        const int s = 2 * r + f;        // sequence index this thread works on

        // DIF stages 1+2 (radix-4, q=128), real input, lanes contiguous
        {
            const float* sq0 = seq[s];
            int i = tl;
            float a0 = sq0[i];
            float a1 = sq0[i + 128];
            float a2 = sq0[i + 256];
            float a3 = sq0[i + 384];
            float w1r = g_twr[i],       w1i = g_twi[i];        // W^i
            float w2r = g_twr[i + 128], w2i = g_twi[i + 128];  // W^{i+128}
            float w3r = g_tw2r[i],      w3i = g_tw2i[i];       // W^{2i}
            float y0 = a0 + a2, y1 = a1 + a3;
            float d02 = a0 - a2, d13 = a1 - a3;
            float y2r = d02 * w1r, y2i = d02 * w1i;
            float y3r = d13 * w2r, y3i = d13 * w2i;
            re[base + i]       = y0 + y1;          im[base + i]       = 0.0f;
            float d01 = y0 - y1;
            re[base + i + 128] = d01 * w3r;        im[base + i + 128] = d01 * w3i;
            re[base + i + 256] = y2r + y3r;        im[base + i + 256] = y2i + y3i;
            float dr = y2r - y3r, di = y2i - y3i;
            re[base + i + 384] = dr * w3r - di * w3i;
            im[base + i + 384] = dr * w3i + di * w3r;
        }
        __syncthreads();

        // DIF stages 3+4 (radix-4, q=32), lanes contiguous in k
        {
            int grp = tl >> 5, k = tl & 31;
            int i0 = base + (grp << 7) + k;
            float x0r = re[i0],      x0i = im[i0];
            float x1r = re[i0 + 32], x1i = im[i0 + 32];
            float x2r = re[i0 + 64], x2i = im[i0 + 64];
            float x3r = re[i0 + 96], x3i = im[i0 + 96];
            float war = g_t4r[k],  wai = g_t4i[k];    // W^{4k}
            float wbr = g_t4br[k], wbi = g_t4bi[k];   // W^{4k+128}
            float wcr = g_t8r[k],  wci = g_t8i[k];    // W^{8k}
            float y0r = x0r + x2r, y0i = x0i + x2i;
            float y1r = x1r + x3r, y1i = x1i + x3i;
            float dar = x0r - x2r, dai = x0i - x2i;
            float dbr = x1r - x3r, dbi = x1i - x3i;
            float y2r = dar * war - dai * wai, y2i = dar * wai + dai * war;
            float y3r = dbr * wbr - dbi * wbi, y3i = dbr * wbi + dbi * wbr;
            re[i0]      = y0r + y1r;  im[i0]      = y0i + y1i;
            float d0r = y0r - y1r, d0i = y0i - y1i;
            re[i0 + 32] = d0r * wcr - d0i * wci;  im[i0 + 32] = d0r * wci + d0i * wcr;
            re[i0 + 64] = y2r + y3r;  im[i0 + 64] = y2i + y3i;
            float d2r = y2r - y3r, d2i = y2i - y3i;
            re[i0 + 96] = d2r * wcr - d2i * wci;  im[i0 + 96] = d2r * wci + d2i * wcr;
        }
        __syncwarp();   // stage34 -> subFFT is warp-local (each warp owns its 128 slots)

        // 32-pt sub-FFTs in registers: warp w owns chunks 4w..4w+3 (its own slots)
        {
            float w16r = g_wstr[lane & 15],       w16i = g_wsti[lane & 15];
            float w8r  = g_wstr[16 + (lane & 7)], w8i  = g_wsti[16 + (lane & 7)];
            float w4r  = g_wstr[24 + (lane & 3)], w4i  = g_wsti[24 + (lane & 3)];
#pragma unroll
            for (int q = 0; q < 4; q++) {
                int cb = ((wid << 2) + q) << 5;    // global chunk base (0..1023)
                float ar = re[cb + lane], ai = im[cb + lane];
                {
                    float pr = __shfl_xor_sync(0xffffffffu, ar, 16);
                    float pi = __shfl_xor_sync(0xffffffffu, ai, 16);
                    bool up = lane & 16;
                    float dr = pr - ar, di = pi - ai;
                    float sr = ar + pr, si = ai + pi;
                    ar = up ? (dr * w16r - di * w16i) : sr;
                    ai = up ? (dr * w16i + di * w16r) : si;
                }
                {
                    float pr = __shfl_xor_sync(0xffffffffu, ar, 8);
                    float pi = __shfl_xor_sync(0xffffffffu, ai, 8);
                    bool up = lane & 8;
                    float dr = pr - ar, di = pi - ai;
                    float sr = ar + pr, si = ai + pi;
                    ar = up ? (dr * w8r - di * w8i) : sr;
                    ai = up ? (dr * w8i + di * w8r) : si;
                }
                {
                    float pr = __shfl_xor_sync(0xffffffffu, ar, 4);
                    float pi = __shfl_xor_sync(0xffffffffu, ai, 4);
                    bool up = lane & 4;
                    float dr = pr - ar, di = pi - ai;
                    float sr = ar + pr, si = ai + pi;
                    ar = up ? (dr * w4r - di * w4i) : sr;
                    ai = up ? (dr * w4i + di * w4r) : si;
                }
                {
                    float pr = __shfl_xor_sync(0xffffffffu, ar, 2);
                    float pi = __shfl_xor_sync(0xffffffffu, ai, 2);
                    bool up = lane & 2;
                    bool j1 = lane & 1;
                    float dr = pr - ar, di = pi - ai;
                    float sr = ar + pr, si = ai + pi;
                    float rr = j1 ? di : dr;
                    float ri = j1 ? -dr : di;
                    ar = up ? rr : sr;
                    ai = up ? ri : si;
                }
                {
                    float pr = __shfl_xor_sync(0xffffffffu, ar, 1);
                    float pi = __shfl_xor_sync(0xffffffffu, ai, 1);
                    bool up = lane & 1;
                    ar = up ? (pr - ar) : (ar + pr);
                    ai = up ? (pi - ai) : (ai + pi);
                }
                float a = sqrtf(ar * ar + ai * ai);
                // storage slot g holds frequency brev9(g&511) of FFT (g>>9).
                // Keep only needed candidates: even p>0 -> idx p/2; p==1 -> idx 0.
                int g = cb + lane;
                int p = g & 511;
                int sl = 2 * r + (g >> 9);
                if ((lane & 1) == 0) {
                    if (p) ampS[sl][p >> 1] = a;
                } else if (p == 1) {
                    ampS[sl][0] = a;
                }
            }
        }
        __syncthreads();   // re/im reuse next round; ampS complete for top-k
    }

    // ---- top-4: warp w -> seq w. idx 0 = freq 256; idx t = freq brev9(2t). ----
    // Tie-break: equal amplitude -> lower frequency.
    if (wid < 4) {
#pragma unroll
        for (int pass = 0; pass < K_; pass++) {
            float bv = -1.0f; int bf = 0x7fffffff;
#pragma unroll
            for (int j = 0; j < 8; j++) {
                int t = lane + 32 * j;
                float vv = ampS[wid][t];
                int   fr = (t == 0) ? 256 : (int)(__brev((unsigned)(2 * t)) >> 23);
                if (vv > bv || (vv == bv && fr < bf)) { bv = vv; bf = fr; }
            }
#pragma unroll
            for (int off = 16; off > 0; off >>= 1) {
                float ov = __shfl_down_sync(0xffffffffu, bv, off);
                int   of = __shfl_down_sync(0xffffffffu, bf, off);
                if (ov > bv || (ov == bv && of < bf)) { bv = ov; bf = of; }
            }
            if (lane == 0) {
                out[KAMP_OFFSET + (size_t)(bn0 + wid) * K_ + pass] = bv;
                int p = (int)(__brev((unsigned)bf) >> 23);   // storage slot of freq
                int wt = (p == 1) ? 0 : (p >> 1);            // ampS index
                ampS[wid][wt] = -2.0f;                       // exclude winner
                int P = T_ / bf;
                P = P < MINP_ ? MINP_ : (P > PMAX_ ? PMAX_ : P);
                int cyc = T_ / P;
                sP[wid][pass] = P; sCyc[wid][pass] = cyc;
                sBase[wid][pass] = T_ - cyc * P;
            }
            __syncwarp();
        }
    }
    __syncthreads();

    // ---- gathered: row-per-warp, 8 warps x 64 rows = all 512 rows ----
    {
#pragma unroll 4
        for (int j = 0; j < 64; j++) {
            int r = wid + 8 * j;             // row id: ((s*4 + k)*32 + c)
            int c = r & 31;
            int k = (r >> 5) & 3;
            int s = r >> 7;
            int P = sP[s][k], cyc = sCyc[s][k];
            int rs = sBase[s][k] + c * P;
            float va = seq[s][min(rs + lane,      T_ - 1)];
            float vb = seq[s][min(rs + lane + 32, T_ - 1)];
            bool crow = (c < cyc);
            float g0 = (crow && lane      < P) ? va : 0.0f;
            float g1 = (crow && lane + 32 < P) ? vb : 0.0f;
            float* gp = out + ((size_t)((bn0 + s) * K_ + k) * CMAX_ + c) * PMAX_;
            __stcs(gp + lane,      g0);
            __stcs(gp + lane + 32, g1);
        }
    }

    // ---- mask: no loads, float4 streaming stores (16 tiles of 8KB each) ----
    {
        float4* mb = (float4*)(out + GATHERED_ELEMS +
                               (size_t)(bn0 * K_) * (CMAX_ * PMAX_)) + tid;
#pragma unroll
        for (int s = 0; s < 4; s++) {
#pragma unroll
            for (int k = 0; k < K_; k++) {
                const int P = sP[s][k], cyc = sCyc[s][k];
#pragma unroll
                for (int i = 0; i < 2; i++) {
                    int e4 = tid + 256 * i;          // float4 index 0..511
                    int c  = e4 >> 4;
                    int p  = (e4 & 15) << 2;
                    float mrow = (c < cyc) ? 1.0f : 0.0f;
                    float4 mv = make_float4((p     < P) ? mrow : 0.0f,
                                            (p + 1 < P) ? mrow : 0.0f,
                                            (p + 2 < P) ? mrow : 0.0f,
                                            (p + 3 < P) ? mrow : 0.0f);
                    __stcs(mb + 256 * i, mv);
                }
                mb += 512;                           // next 8KB tile
            }
        }
    }
}

// ---------------------------------------------------------------------------
extern "C" void kernel_launch(void* const* d_in, const int* in_sizes, int n_in,
                              void* d_out, int out_size) {
    const float* x = (const float*)d_in[0];
    float* out = (float*)d_out;

    pt_init<<<4, 128>>>();
    pt_fused<<<BN_ / 4, 256>>>(x, out);
}

// round 12
// speedup vs baseline: 1.1911x; 1.1911x over previous
#include <cuda_runtime.h>
#include <cuda_bf16.h>

#define B_    32
#define T_    512
#define N_    128
#define BN_   4096
#define K_    4
#define PMAX_ 64
#define MINP_ 16
#define CMAX_ 32   // T/MINP

#define GATHERED_ELEMS 33554432ull   // 32*128*4*32*64
#define KAMP_OFFSET    67108864ull   // 2 * GATHERED_ELEMS

#define SSTRIDE 520                  // padded length of each shifted copy (16B-aligned)

// ---------------------------------------------------------------------------
// Fused kernel: one block (256 threads) per PAIR of sequences.
// DIF radix-4 FFT (natural-order input, register sub-FFTs via shfl), top-k in
// bit-reversed storage, then gather via SHIFTED smem copies: any unaligned
// 4-float window is one aligned conflict-free LDS.128; all stores STG.128.
// Twiddles computed inline via sincospif (no init kernel, no table loads):
//   W^{e+128} = W^e * (-i)  -> derived by component swap.
// ---------------------------------------------------------------------------
__global__ __launch_bounds__(256, 8) void pt_fused(const float* __restrict__ x,
                                                   float* __restrict__ out) {
    __shared__ float sh[2][4][SSTRIDE];         // shifted copies: sh[s][a][i]=seq_s[i+a]
    __shared__ float re[1024], im[1024];        // FFT workspace; re becomes amp
    __shared__ int   sP[2][4], sCyc[2][4], sBase[2][4];

    const int bn0  = blockIdx.x * 2;
    const int tid  = threadIdx.x;
    const int lane = tid & 31;
    const int wid  = tid >> 5;

    // ---- load both sequences; write 4 shifted copies each (conflict-free STS) ----
    {
        const int b  = bn0 >> 7;
        const int n0 = bn0 & 127;
        const float2* xp = (const float2*)(x + (size_t)b * T_ * N_ + n0);
        float2 v0 = xp[(size_t)tid * (N_ / 2)];
        float2 v1 = xp[(size_t)(tid + 256) * (N_ / 2)];
        int t1 = tid + 256;
#pragma unroll
        for (int a = 0; a < 4; a++) {
            if (tid >= a) { sh[0][a][tid - a] = v0.x; sh[1][a][tid - a] = v0.y; }
            sh[0][a][t1 - a] = v1.x; sh[1][a][t1 - a] = v1.y;
        }
    }
    __syncthreads();

    const int ffti = tid >> 7;          // which FFT this thread works on
    const int base = ffti << 9;
    const int tl   = tid & 127;

    // ---- DIF stages 1+2 (radix-4, q=128), real input, lanes contiguous ----
    {
        const float* sq0 = sh[ffti][0];
        int i = tl;
        float a0 = sq0[i];
        float a1 = sq0[i + 128];
        float a2 = sq0[i + 256];
        float a3 = sq0[i + 384];
        float w1r, w1i, w3r, w3i;
        sincospif(-(float)i / 256.f, &w1i, &w1r);          // W^i
        sincospif(-(float)i / 128.f, &w3i, &w3r);          // W^{2i}
        // W^{i+128} = W^i * (-i):
        float w2r = w1i, w2i = -w1r;
        float y0 = a0 + a2, y1 = a1 + a3;
        float d02 = a0 - a2, d13 = a1 - a3;
        float y2r = d02 * w1r, y2i = d02 * w1i;
        float y3r = d13 * w2r, y3i = d13 * w2i;
        re[base + i]       = y0 + y1;          im[base + i]       = 0.0f;
        float d01 = y0 - y1;
        re[base + i + 128] = d01 * w3r;        im[base + i + 128] = d01 * w3i;
        re[base + i + 256] = y2r + y3r;        im[base + i + 256] = y2i + y3i;
        float dr = y2r - y3r, di = y2i - y3i;
        re[base + i + 384] = dr * w3r - di * w3i;
        im[base + i + 384] = dr * w3i + di * w3r;
    }
    __syncthreads();

    // ---- DIF stages 3+4 (radix-4, q=32), lanes contiguous in k ----
    {
        int grp = tl >> 5, k = tl & 31;
        int i0 = base + (grp << 7) + k;
        float x0r = re[i0],      x0i = im[i0];
        float x1r = re[i0 + 32], x1i = im[i0 + 32];
        float x2r = re[i0 + 64], x2i = im[i0 + 64];
        float x3r = re[i0 + 96], x3i = im[i0 + 96];
        float war, wai, wcr, wci;
        sincospif(-(float)k / 64.f, &wai, &war);           // W^{4k}
        sincospif(-(float)k / 32.f, &wci, &wcr);           // W^{8k}
        // W^{4k+128} = W^{4k} * (-i):
        float wbr = wai, wbi = -war;
        float y0r = x0r + x2r, y0i = x0i + x2i;
        float y1r = x1r + x3r, y1i = x1i + x3i;
        float dar = x0r - x2r, dai = x0i - x2i;
        float dbr = x1r - x3r, dbi = x1i - x3i;
        float y2r = dar * war - dai * wai, y2i = dar * wai + dai * war;
        float y3r = dbr * wbr - dbi * wbi, y3i = dbr * wbi + dbi * wbr;
        re[i0]      = y0r + y1r;  im[i0]      = y0i + y1i;
        float d0r = y0r - y1r, d0i = y0i - y1i;
        re[i0 + 32] = d0r * wcr - d0i * wci;  im[i0 + 32] = d0r * wci + d0i * wcr;
        re[i0 + 64] = y2r + y3r;  im[i0 + 64] = y2i + y3i;
        float d2r = y2r - y3r, d2i = y2i - y3i;
        re[i0 + 96] = d2r * wcr - d2i * wci;  im[i0 + 96] = d2r * wci + d2i * wcr;
    }
    __syncthreads();

    // ---- 32-pt sub-FFTs in registers: warp w owns chunks 4w..4w+3 ----
    {
        float w16r, w16i, w8r, w8i, w4r, w4i;
        sincospif(-(float)(lane & 15) / 16.f, &w16i, &w16r);  // W^{16j}
        sincospif(-(float)(lane & 7)  /  8.f, &w8i,  &w8r);   // W^{32j}
        sincospif(-(float)(lane & 3)  /  4.f, &w4i,  &w4r);   // W^{64j}
#pragma unroll
        for (int q = 0; q < 4; q++) {
            int cb = ((wid << 2) + q) << 5;        // chunk base in storage
            float ar = re[cb + lane], ai = im[cb + lane];
            {
                float pr = __shfl_xor_sync(0xffffffffu, ar, 16);
                float pi = __shfl_xor_sync(0xffffffffu, ai, 16);
                bool up = lane & 16;
                float dr = pr - ar, di = pi - ai;
                float sr = ar + pr, si = ai + pi;
                ar = up ? (dr * w16r - di * w16i) : sr;
                ai = up ? (dr * w16i + di * w16r) : si;
            }
            {
                float pr = __shfl_xor_sync(0xffffffffu, ar, 8);
                float pi = __shfl_xor_sync(0xffffffffu, ai, 8);
                bool up = lane & 8;
                float dr = pr - ar, di = pi - ai;
                float sr = ar + pr, si = ai + pi;
                ar = up ? (dr * w8r - di * w8i) : sr;
                ai = up ? (dr * w8i + di * w8r) : si;
            }
            {
                float pr = __shfl_xor_sync(0xffffffffu, ar, 4);
                float pi = __shfl_xor_sync(0xffffffffu, ai, 4);
                bool up = lane & 4;
                float dr = pr - ar, di = pi - ai;
                float sr = ar + pr, si = ai + pi;
                ar = up ? (dr * w4r - di * w4i) : sr;
                ai = up ? (dr * w4i + di * w4r) : si;
            }
            {
                float pr = __shfl_xor_sync(0xffffffffu, ar, 2);
                float pi = __shfl_xor_sync(0xffffffffu, ai, 2);
                bool up = lane & 2;
                bool j1 = lane & 1;
                float dr = pr - ar, di = pi - ai;
                float sr = ar + pr, si = ai + pi;
                float rr = j1 ? di : dr;
                float ri = j1 ? -dr : di;
                ar = up ? rr : sr;
                ai = up ? ri : si;
            }
            {
                float pr = __shfl_xor_sync(0xffffffffu, ar, 1);
                float pi = __shfl_xor_sync(0xffffffffu, ai, 1);
                bool up = lane & 1;
                ar = up ? (pr - ar) : (ar + pr);
                ai = up ? (pi - ai) : (ai + pi);
            }
            re[cb + lane] = sqrtf(ar * ar + ai * ai);   // amp into re
        }
    }
    __syncthreads();

    // ---- top-4: warp 0 -> seq A, warp 1 -> seq B (smem re-scan) ----
    // Storage slot p holds frequency brev9(p). Candidates = bins 1..256:
    // t=0 -> p=1 (freq 256); t>=1 -> p=2t (freqs 1..255). Tie-break: lower freq.
    if (wid < 2) {
        const int fbase = wid << 9;
#pragma unroll
        for (int pass = 0; pass < K_; pass++) {
            float bv = -1.0f; int bf = 0x7fffffff;
#pragma unroll
            for (int j = 0; j < 8; j++) {
                int t = lane + 32 * j;
                int p = (t == 0) ? 1 : (2 * t);
                float vv = re[fbase + p];
                int   f  = (int)(__brev((unsigned)p) >> 23);
                if (vv > bv || (vv == bv && f < bf)) { bv = vv; bf = f; }
            }
#pragma unroll
            for (int off = 16; off > 0; off >>= 1) {
                float ov = __shfl_down_sync(0xffffffffu, bv, off);
                int   of = __shfl_down_sync(0xffffffffu, bf, off);
                if (ov > bv || (ov == bv && of < bf)) { bv = ov; bf = of; }
            }
            if (lane == 0) {
                out[KAMP_OFFSET + (size_t)(bn0 + wid) * K_ + pass] = bv;
                re[fbase + (int)(__brev((unsigned)bf) >> 23)] = -2.0f; // exclude
                int P = T_ / bf;                       // bf = frequency >= 1
                P = P < MINP_ ? MINP_ : (P > PMAX_ ? PMAX_ : P);
                int cyc = T_ / P;
                sP[wid][pass] = P; sCyc[wid][pass] = cyc;
                sBase[wid][pass] = T_ - cyc * P;
            }
            __syncwarp();
        }
    }
    __syncthreads();

    // ---- gather + mask: one LDS.128 + two STG.128 per float4 chunk ----
    // Window seq[off..off+3] (any alignment) = aligned float4 of copy a=off&3.
    // Masked components select 0 (FSEL: no NaN leak from garbage smem).
    {
        float4* gb = (float4*)(out + (size_t)(bn0 * K_) * (CMAX_ * PMAX_)) + tid;
        float4* mb = (float4*)(out + GATHERED_ELEMS +
                               (size_t)(bn0 * K_) * (CMAX_ * PMAX_)) + tid;
#pragma unroll
        for (int sidx = 0; sidx < 2; sidx++) {
#pragma unroll
            for (int k = 0; k < K_; k++) {
                const int P = sP[sidx][k], cyc = sCyc[sidx][k], bas = sBase[sidx][k];
#pragma unroll
                for (int i = 0; i < 2; i++) {
                    int e4 = tid + 256 * i;          // float4 index 0..511
                    int c  = e4 >> 4;                // cycle row
                    int p  = (e4 & 15) << 2;         // position in period
                    int off = bas + c * P + p;
                    int idx4 = min(off >> 2, (SSTRIDE - 4) >> 2);
                    float4 v = *((const float4*)sh[sidx][off & 3] + idx4);
                    bool crow = (c < cyc);
                    bool b0 = crow && (p     < P);
                    bool b1 = crow && (p + 1 < P);
                    bool b2 = crow && (p + 2 < P);
                    bool b3 = crow && (p + 3 < P);
                    float4 g = make_float4(b0 ? v.x : 0.0f, b1 ? v.y : 0.0f,
                                           b2 ? v.z : 0.0f, b3 ? v.w : 0.0f);
                    float4 m = make_float4(b0 ? 1.0f : 0.0f, b1 ? 1.0f : 0.0f,
                                           b2 ? 1.0f : 0.0f, b3 ? 1.0f : 0.0f);
                    __stcs(gb + 256 * i, g);
                    __stcs(mb + 256 * i, m);
                }
                gb += 512;  mb += 512;               // next 8KB tile
            }
        }
    }
}

// ---------------------------------------------------------------------------
extern "C" void kernel_launch(void* const* d_in, const int* in_sizes, int n_in,
                              void* d_out, int out_size) {
    const float* x = (const float*)d_in[0];
    float* out = (float*)d_out;

    pt_fused<<<BN_ / 2, 256>>>(x, out);
}